// round 1
// baseline (speedup 1.0000x reference)
#include <cuda_runtime.h>
#include <math.h>

#define Bz 2
#define Sq 4096
#define Dm 512
#define Hh 8
#define Hd 64
#define Mrows (Bz*Sq)           // 8192
#define INV_SQRT_D 0.044194173824159216f   // 1/sqrt(512)

// Scratch (static device allocations — allowed; no cudaMalloc anywhere)
__device__ float g_q[(size_t)Bz*Hh*Sq*Hd];    // [B,H,S,Hd]
__device__ float g_k[(size_t)Bz*Hh*Sq*Hd];
__device__ float g_v[(size_t)Bz*Hh*Sq*Hd];
__device__ float g_ctx[(size_t)Mrows*Dm];     // [B*S, D] attention output (heads concatenated)

// ---------------------------------------------------------------------------
// QKV projection: out = x @ W + b, remapped to [B,H,S,Hd]
// grid: (N/64, M/64, 3)   block: (16,16)
// ---------------------------------------------------------------------------
__global__ void proj_qkv_kernel(const float* __restrict__ x,
                                const float* __restrict__ Wq, const float* __restrict__ bq,
                                const float* __restrict__ Wk, const float* __restrict__ bk,
                                const float* __restrict__ Wv, const float* __restrict__ bv)
{
    const int which = blockIdx.z;
    const float* __restrict__ W    = (which == 0) ? Wq : (which == 1) ? Wk : Wv;
    const float* __restrict__ bias = (which == 0) ? bq : (which == 1) ? bk : bv;
    float* __restrict__ out        = (which == 0) ? g_q : (which == 1) ? g_k : g_v;

    __shared__ float Ast[32][68];   // A tile transposed: Ast[k][r]
    __shared__ float Ws[32][68];    // W tile: Ws[k][c]

    const int tx = threadIdx.x, ty = threadIdx.y;
    const int tid = ty * 16 + tx;
    const int row0 = blockIdx.y * 64;
    const int col0 = blockIdx.x * 64;

    float acc[4][4] = {};

    for (int k0 = 0; k0 < Dm; k0 += 32) {
        // Load A tile (64 rows x 32 k), transpose into smem
        #pragma unroll
        for (int i = 0; i < 2; i++) {
            int f = tid + i * 256;          // 0..511 float4s
            int r  = f >> 3;                // 8 float4 per row
            int kq = f & 7;
            float4 v = *(const float4*)&x[(size_t)(row0 + r) * Dm + k0 + kq * 4];
            Ast[kq * 4 + 0][r] = v.x;
            Ast[kq * 4 + 1][r] = v.y;
            Ast[kq * 4 + 2][r] = v.z;
            Ast[kq * 4 + 3][r] = v.w;
        }
        // Load W tile (32 k x 64 cols)
        #pragma unroll
        for (int i = 0; i < 2; i++) {
            int f = tid + i * 256;
            int k  = f >> 4;                // 16 float4 per row
            int cq = f & 15;
            float4 v = *(const float4*)&W[(size_t)(k0 + k) * Dm + col0 + cq * 4];
            *(float4*)&Ws[k][cq * 4] = v;
        }
        __syncthreads();

        #pragma unroll
        for (int k = 0; k < 32; k++) {
            float4 a = *(const float4*)&Ast[k][ty * 4];
            float4 b = *(const float4*)&Ws[k][tx * 4];
            float av[4] = {a.x, a.y, a.z, a.w};
            float bv4[4] = {b.x, b.y, b.z, b.w};
            #pragma unroll
            for (int i = 0; i < 4; i++)
                #pragma unroll
                for (int j = 0; j < 4; j++)
                    acc[i][j] += av[i] * bv4[j];
        }
        __syncthreads();
    }

    // Epilogue: bias + remap to [B,H,S,Hd]
    #pragma unroll
    for (int i = 0; i < 4; i++) {
        int m = row0 + ty * 4 + i;
        int b = m / Sq, s = m % Sq;
        #pragma unroll
        for (int j = 0; j < 4; j++) {
            int n = col0 + tx * 4 + j;
            int h = n / Hd, d = n % Hd;
            out[(((size_t)(b * Hh + h) * Sq) + s) * Hd + d] = acc[i][j] + bias[n];
        }
    }
}

// ---------------------------------------------------------------------------
// Flash attention (fp32, online softmax).
// grid: (S/64, B*H)   block: 256 (16x16 logical)
// Dynamic smem layout (floats):
//   Qt  [64][68]  (Qt[k][r])
//   KV  [64][68]  (K transposed Kc[k][c], then reused as V[k][c])
//   St  [64][68]  (scores/probs transposed: St[kv][q])
//   mrow[64] lrow[64] arow[64] maxpart[4*64] sumpart[4*64]
// ---------------------------------------------------------------------------
#define ATT_TILE_F (64 * 68)
#define ATT_SMEM_FLOATS (3 * ATT_TILE_F + 64 * 3 + 2 * 4 * 64)
#define ATT_SMEM_BYTES (ATT_SMEM_FLOATS * 4)

__global__ void attn_kernel()
{
    extern __shared__ float sm[];
    float (*Qt)[68] = (float (*)[68])sm;
    float (*KV)[68] = (float (*)[68])(sm + ATT_TILE_F);
    float (*St)[68] = (float (*)[68])(sm + 2 * ATT_TILE_F);
    float* mrow    = sm + 3 * ATT_TILE_F;
    float* lrow    = mrow + 64;
    float* arow    = lrow + 64;
    float* maxpart = arow + 64;      // [4][64]
    float* sumpart = maxpart + 256;  // [4][64]

    const int tid = threadIdx.x;
    const int tx = tid & 15, ty = tid >> 4;
    const int qt = blockIdx.x;
    const int bh = blockIdx.y;

    const float* __restrict__ Qg = g_q + (size_t)bh * Sq * Hd + (size_t)qt * 64 * Hd;
    const float* __restrict__ Kg = g_k + (size_t)bh * Sq * Hd;
    const float* __restrict__ Vg = g_v + (size_t)bh * Sq * Hd;

    if (tid < 64) { mrow[tid] = -INFINITY; lrow[tid] = 0.0f; }

    // Load Q tile transposed: Qt[k][r] = Q[r][k]
    #pragma unroll
    for (int i = 0; i < 4; i++) {
        int f = tid + i * 256;       // 0..1023 float4s
        int r  = f >> 4;             // 16 float4 per row of 64
        int kq = f & 15;
        float4 v = *(const float4*)&Qg[(size_t)r * Hd + kq * 4];
        Qt[kq * 4 + 0][r] = v.x;
        Qt[kq * 4 + 1][r] = v.y;
        Qt[kq * 4 + 2][r] = v.z;
        Qt[kq * 4 + 3][r] = v.w;
    }
    __syncthreads();

    float o[4][4] = {};

    for (int kt = 0; kt < Sq / 64; kt++) {
        const int kvbase = kt * 64;

        // Load K tile transposed: KV[k][c] = K[c][k]
        #pragma unroll
        for (int i = 0; i < 4; i++) {
            int f = tid + i * 256;
            int c  = f >> 4;
            int kq = f & 15;
            float4 v = *(const float4*)&Kg[(size_t)(kvbase + c) * Hd + kq * 4];
            KV[kq * 4 + 0][c] = v.x;
            KV[kq * 4 + 1][c] = v.y;
            KV[kq * 4 + 2][c] = v.z;
            KV[kq * 4 + 3][c] = v.w;
        }
        __syncthreads();

        // S = Q @ K^T * scale ; stored transposed: St[c][r]
        {
            float s4[4][4] = {};
            #pragma unroll
            for (int k = 0; k < 64; k++) {
                float4 a = *(const float4*)&Qt[k][ty * 4];
                float4 b = *(const float4*)&KV[k][tx * 4];
                float av[4] = {a.x, a.y, a.z, a.w};
                float bv4[4] = {b.x, b.y, b.z, b.w};
                #pragma unroll
                for (int i = 0; i < 4; i++)
                    #pragma unroll
                    for (int j = 0; j < 4; j++)
                        s4[i][j] += av[i] * bv4[j];
            }
            #pragma unroll
            for (int i = 0; i < 4; i++)
                #pragma unroll
                for (int j = 0; j < 4; j++)
                    St[tx * 4 + j][ty * 4 + i] = s4[i][j] * INV_SQRT_D;
        }
        __syncthreads();

        // Softmax phase A: partial row max (row = q index r)
        {
            int r = tid & 63, g = tid >> 6;
            float pm = -INFINITY;
            #pragma unroll
            for (int cc = 0; cc < 16; cc++)
                pm = fmaxf(pm, St[g * 16 + cc][r]);
            maxpart[g * 64 + r] = pm;
        }
        __syncthreads();

        // Phase B: new max / alpha
        if (tid < 64) {
            int r = tid;
            float mnew = mrow[r];
            #pragma unroll
            for (int g = 0; g < 4; g++) mnew = fmaxf(mnew, maxpart[g * 64 + r]);
            arow[r] = __expf(mrow[r] - mnew);
            mrow[r] = mnew;
        }
        __syncthreads();

        // Phase C: exponentiate + partial sums; rescale O accumulators
        {
            int r = tid & 63, g = tid >> 6;
            float m = mrow[r];
            float ps = 0.0f;
            #pragma unroll
            for (int cc = 0; cc < 16; cc++) {
                int c = g * 16 + cc;
                float p = __expf(St[c][r] - m);
                St[c][r] = p;
                ps += p;
            }
            sumpart[g * 64 + r] = ps;
        }
        #pragma unroll
        for (int i = 0; i < 4; i++) {
            float al = arow[ty * 4 + i];
            #pragma unroll
            for (int j = 0; j < 4; j++) o[i][j] *= al;
        }
        __syncthreads();

        // Phase D (l update) + load V tile (direct layout KV[k][c])
        if (tid < 64) {
            int r = tid;
            float l = lrow[r] * arow[r];
            #pragma unroll
            for (int g = 0; g < 4; g++) l += sumpart[g * 64 + r];
            lrow[r] = l;
        }
        #pragma unroll
        for (int i = 0; i < 4; i++) {
            int f = tid + i * 256;
            int k  = f >> 4;
            int cq = f & 15;
            float4 v = *(const float4*)&Vg[(size_t)(kvbase + k) * Hd + cq * 4];
            *(float4*)&KV[k][cq * 4] = v;
        }
        __syncthreads();

        // O += P @ V  (P = St[k][r], V = KV[k][c])
        #pragma unroll
        for (int k = 0; k < 64; k++) {
            float4 a = *(const float4*)&St[k][ty * 4];
            float4 b = *(const float4*)&KV[k][tx * 4];
            float av[4] = {a.x, a.y, a.z, a.w};
            float bv4[4] = {b.x, b.y, b.z, b.w};
            #pragma unroll
            for (int i = 0; i < 4; i++)
                #pragma unroll
                for (int j = 0; j < 4; j++)
                    o[i][j] += av[i] * bv4[j];
        }
        __syncthreads();
    }

    // Finalize: divide by l, write to g_ctx in [B*S, D] layout (heads concat)
    const int b = bh / Hh, h = bh % Hh;
    #pragma unroll
    for (int i = 0; i < 4; i++) {
        int r = ty * 4 + i;
        float inv = 1.0f / lrow[r];
        int s = qt * 64 + r;
        float4 v = make_float4(o[i][0] * inv, o[i][1] * inv, o[i][2] * inv, o[i][3] * inv);
        *(float4*)&g_ctx[((size_t)(b * Sq + s)) * Dm + h * Hd + tx * 4] = v;
    }
}

// ---------------------------------------------------------------------------
// Output projection: d_out = g_ctx @ Wo + bo   (plain [M,N] output)
// grid: (N/64, M/64)   block: (16,16)
// ---------------------------------------------------------------------------
__global__ void proj_out_kernel(const float* __restrict__ Wo,
                                const float* __restrict__ bo,
                                float* __restrict__ out)
{
    __shared__ float Ast[32][68];
    __shared__ float Ws[32][68];

    const int tx = threadIdx.x, ty = threadIdx.y;
    const int tid = ty * 16 + tx;
    const int row0 = blockIdx.y * 64;
    const int col0 = blockIdx.x * 64;

    float acc[4][4] = {};

    for (int k0 = 0; k0 < Dm; k0 += 32) {
        #pragma unroll
        for (int i = 0; i < 2; i++) {
            int f = tid + i * 256;
            int r  = f >> 3;
            int kq = f & 7;
            float4 v = *(const float4*)&g_ctx[(size_t)(row0 + r) * Dm + k0 + kq * 4];
            Ast[kq * 4 + 0][r] = v.x;
            Ast[kq * 4 + 1][r] = v.y;
            Ast[kq * 4 + 2][r] = v.z;
            Ast[kq * 4 + 3][r] = v.w;
        }
        #pragma unroll
        for (int i = 0; i < 2; i++) {
            int f = tid + i * 256;
            int k  = f >> 4;
            int cq = f & 15;
            float4 v = *(const float4*)&Wo[(size_t)(k0 + k) * Dm + col0 + cq * 4];
            *(float4*)&Ws[k][cq * 4] = v;
        }
        __syncthreads();

        #pragma unroll
        for (int k = 0; k < 32; k++) {
            float4 a = *(const float4*)&Ast[k][ty * 4];
            float4 b = *(const float4*)&Ws[k][tx * 4];
            float av[4] = {a.x, a.y, a.z, a.w};
            float bv4[4] = {b.x, b.y, b.z, b.w};
            #pragma unroll
            for (int i = 0; i < 4; i++)
                #pragma unroll
                for (int j = 0; j < 4; j++)
                    acc[i][j] += av[i] * bv4[j];
        }
        __syncthreads();
    }

    #pragma unroll
    for (int i = 0; i < 4; i++) {
        int m = row0 + ty * 4 + i;
        #pragma unroll
        for (int j = 0; j < 4; j++) {
            int n = col0 + tx * 4 + j;
            out[(size_t)m * Dm + n] = acc[i][j] + bo[n];
        }
    }
}

// ---------------------------------------------------------------------------
extern "C" void kernel_launch(void* const* d_in, const int* in_sizes, int n_in,
                              void* d_out, int out_size)
{
    const float* x  = (const float*)d_in[0];
    const float* Wq = (const float*)d_in[1];
    const float* bq = (const float*)d_in[2];
    const float* Wk = (const float*)d_in[3];
    const float* bk = (const float*)d_in[4];
    const float* Wv = (const float*)d_in[5];
    const float* bv = (const float*)d_in[6];
    const float* Wo = (const float*)d_in[7];
    const float* bo = (const float*)d_in[8];
    float* out = (float*)d_out;

    cudaFuncSetAttribute(attn_kernel, cudaFuncAttributeMaxDynamicSharedMemorySize,
                         ATT_SMEM_BYTES);

    dim3 blk(16, 16);
    proj_qkv_kernel<<<dim3(Dm / 64, Mrows / 64, 3), blk>>>(x, Wq, bq, Wk, bk, Wv, bv);
    attn_kernel<<<dim3(Sq / 64, Bz * Hh), 256, ATT_SMEM_BYTES>>>();
    proj_out_kernel<<<dim3(Dm / 64, Mrows / 64), blk>>>(Wo, bo, out);
}

// round 2
// speedup vs baseline: 3.2356x; 3.2356x over previous
#include <cuda_runtime.h>
#include <math.h>
#include <stdint.h>

#define Bz 2
#define Sq 4096
#define Dm 512
#define Hh 8
#define Hd 64
#define Mrows (Bz*Sq)           // 8192
#define INV_SQRT_D 0.044194173824159216f   // 1/sqrt(512)

// Scratch (static device arrays — no cudaMalloc anywhere)
__device__ float g_q[(size_t)Bz*Hh*Sq*Hd];    // [B,H,S,Hd]
__device__ float g_k[(size_t)Bz*Hh*Sq*Hd];
__device__ float g_v[(size_t)Bz*Hh*Sq*Hd];
__device__ float g_ctx[(size_t)Mrows*Dm];     // [B*S, D]

// ---------------------------------------------------------------------------
// tf32 helpers
// ---------------------------------------------------------------------------
__device__ __forceinline__ uint32_t f2tf(float x) {
    uint32_t t;
    asm("cvt.rna.tf32.f32 %0, %1;" : "=r"(t) : "f"(x));
    return t;
}

__device__ __forceinline__ void mma_tf32(float* c,  // c[4]
                                         uint32_t a0, uint32_t a1, uint32_t a2, uint32_t a3,
                                         uint32_t b0, uint32_t b1) {
    asm volatile(
        "mma.sync.aligned.m16n8k8.row.col.f32.tf32.tf32.f32 "
        "{%0,%1,%2,%3},{%4,%5,%6,%7},{%8,%9},{%0,%1,%2,%3};"
        : "+f"(c[0]), "+f"(c[1]), "+f"(c[2]), "+f"(c[3])
        : "r"(a0), "r"(a1), "r"(a2), "r"(a3), "r"(b0), "r"(b1));
}

__device__ __forceinline__ uint32_t ldsb(const float* p) {
    return __float_as_uint(*p);
}

// ===========================================================================
// Projection GEMM (tf32 mma): out = x @ W + b, remapped to [B,H,S,Hd]
// tile: 128(M) x 64(N), K chunk 32. block 256 (8 warps, 16 rows each).
// grid: (8, 64, 3)
// ===========================================================================
#define PA 36   // A pad (mod32 == 4)
#define PW 72   // W pad (mod32 == 8)

__global__ __launch_bounds__(256, 2)
void proj_qkv_kernel(const float* __restrict__ x,
                     const float* __restrict__ Wq, const float* __restrict__ bq,
                     const float* __restrict__ Wk, const float* __restrict__ bk,
                     const float* __restrict__ Wv, const float* __restrict__ bv)
{
    const int which = blockIdx.z;
    const float* __restrict__ W    = (which == 0) ? Wq : (which == 1) ? Wk : Wv;
    const float* __restrict__ bias = (which == 0) ? bq : (which == 1) ? bk : bv;
    float* __restrict__ out        = (which == 0) ? g_q : (which == 1) ? g_k : g_v;

    __shared__ float Ash[128][PA];
    __shared__ float Wsh[32][PW];

    const int tid = threadIdx.x, lane = tid & 31, warp = tid >> 5;
    const int quad = lane >> 2, tg = lane & 3;
    const int row0 = warp * 16 + quad;          // thread's base row in tile
    const int m0g  = blockIdx.y * 128;
    const int col0 = blockIdx.x * 64;

    float acc[8][4];
    #pragma unroll
    for (int nb = 0; nb < 8; nb++)
        #pragma unroll
        for (int j = 0; j < 4; j++) acc[nb][j] = 0.0f;

    for (int k0 = 0; k0 < Dm; k0 += 32) {
        // A tile: 128 rows x 32 k   (1024 float4 / 256 thr = 4 each)
        #pragma unroll
        for (int i = 0; i < 4; i++) {
            int idx = tid + i * 256;
            int r = idx >> 3, cq = idx & 7;
            float4 v = *(const float4*)&x[(size_t)(m0g + r) * Dm + k0 + cq * 4];
            float4 w;
            w.x = __uint_as_float(f2tf(v.x)); w.y = __uint_as_float(f2tf(v.y));
            w.z = __uint_as_float(f2tf(v.z)); w.w = __uint_as_float(f2tf(v.w));
            *(float4*)&Ash[r][cq * 4] = w;
        }
        // W tile: 32 k x 64 n  (512 float4 / 256 = 2 each)
        #pragma unroll
        for (int i = 0; i < 2; i++) {
            int idx = tid + i * 256;
            int r = idx >> 4, cq = idx & 15;
            float4 v = *(const float4*)&W[(size_t)(k0 + r) * Dm + col0 + cq * 4];
            float4 w;
            w.x = __uint_as_float(f2tf(v.x)); w.y = __uint_as_float(f2tf(v.y));
            w.z = __uint_as_float(f2tf(v.z)); w.w = __uint_as_float(f2tf(v.w));
            *(float4*)&Wsh[r][cq * 4] = w;
        }
        __syncthreads();

        #pragma unroll
        for (int kc = 0; kc < 4; kc++) {
            uint32_t a0 = ldsb(&Ash[row0    ][kc * 8 + tg]);
            uint32_t a1 = ldsb(&Ash[row0 + 8][kc * 8 + tg]);
            uint32_t a2 = ldsb(&Ash[row0    ][kc * 8 + tg + 4]);
            uint32_t a3 = ldsb(&Ash[row0 + 8][kc * 8 + tg + 4]);
            #pragma unroll
            for (int nb = 0; nb < 8; nb++) {
                uint32_t b0 = ldsb(&Wsh[kc * 8 + tg    ][nb * 8 + quad]);
                uint32_t b1 = ldsb(&Wsh[kc * 8 + tg + 4][nb * 8 + quad]);
                mma_tf32(acc[nb], a0, a1, a2, a3, b0, b1);
            }
        }
        __syncthreads();
    }

    // Epilogue: bias + remap [B,H,S,Hd]. h == blockIdx.x (64-wide tile).
    const int h = blockIdx.x;
    #pragma unroll
    for (int nb = 0; nb < 8; nb++) {
        int d = nb * 8 + 2 * tg;
        float b0v = bias[col0 + d], b1v = bias[col0 + d + 1];
        int m = m0g + row0;
        int b = m >> 12, s = m & 4095;
        float2 v0 = make_float2(acc[nb][0] + b0v, acc[nb][1] + b1v);
        *(float2*)&out[(((size_t)(b * Hh + h) * Sq) + s) * Hd + d] = v0;
        m = m0g + row0 + 8;
        b = m >> 12; s = m & 4095;
        float2 v1 = make_float2(acc[nb][2] + b0v, acc[nb][3] + b1v);
        *(float2*)&out[(((size_t)(b * Hh + h) * Sq) + s) * Hd + d] = v1;
    }
}

// ===========================================================================
// Output projection GEMM (tf32 mma): d_out = g_ctx @ Wo + bo
// grid: (8, 64)
// ===========================================================================
__global__ __launch_bounds__(256, 2)
void proj_out_kernel(const float* __restrict__ Wo,
                     const float* __restrict__ bo,
                     float* __restrict__ out)
{
    __shared__ float Ash[128][PA];
    __shared__ float Wsh[32][PW];

    const int tid = threadIdx.x, lane = tid & 31, warp = tid >> 5;
    const int quad = lane >> 2, tg = lane & 3;
    const int row0 = warp * 16 + quad;
    const int m0g  = blockIdx.y * 128;
    const int col0 = blockIdx.x * 64;

    float acc[8][4];
    #pragma unroll
    for (int nb = 0; nb < 8; nb++)
        #pragma unroll
        for (int j = 0; j < 4; j++) acc[nb][j] = 0.0f;

    for (int k0 = 0; k0 < Dm; k0 += 32) {
        #pragma unroll
        for (int i = 0; i < 4; i++) {
            int idx = tid + i * 256;
            int r = idx >> 3, cq = idx & 7;
            float4 v = *(const float4*)&g_ctx[(size_t)(m0g + r) * Dm + k0 + cq * 4];
            float4 w;
            w.x = __uint_as_float(f2tf(v.x)); w.y = __uint_as_float(f2tf(v.y));
            w.z = __uint_as_float(f2tf(v.z)); w.w = __uint_as_float(f2tf(v.w));
            *(float4*)&Ash[r][cq * 4] = w;
        }
        #pragma unroll
        for (int i = 0; i < 2; i++) {
            int idx = tid + i * 256;
            int r = idx >> 4, cq = idx & 15;
            float4 v = *(const float4*)&Wo[(size_t)(k0 + r) * Dm + col0 + cq * 4];
            float4 w;
            w.x = __uint_as_float(f2tf(v.x)); w.y = __uint_as_float(f2tf(v.y));
            w.z = __uint_as_float(f2tf(v.z)); w.w = __uint_as_float(f2tf(v.w));
            *(float4*)&Wsh[r][cq * 4] = w;
        }
        __syncthreads();

        #pragma unroll
        for (int kc = 0; kc < 4; kc++) {
            uint32_t a0 = ldsb(&Ash[row0    ][kc * 8 + tg]);
            uint32_t a1 = ldsb(&Ash[row0 + 8][kc * 8 + tg]);
            uint32_t a2 = ldsb(&Ash[row0    ][kc * 8 + tg + 4]);
            uint32_t a3 = ldsb(&Ash[row0 + 8][kc * 8 + tg + 4]);
            #pragma unroll
            for (int nb = 0; nb < 8; nb++) {
                uint32_t b0 = ldsb(&Wsh[kc * 8 + tg    ][nb * 8 + quad]);
                uint32_t b1 = ldsb(&Wsh[kc * 8 + tg + 4][nb * 8 + quad]);
                mma_tf32(acc[nb], a0, a1, a2, a3, b0, b1);
            }
        }
        __syncthreads();
    }

    #pragma unroll
    for (int nb = 0; nb < 8; nb++) {
        int n = col0 + nb * 8 + 2 * tg;
        float b0v = bo[n], b1v = bo[n + 1];
        *(float2*)&out[(size_t)(m0g + row0) * Dm + n] =
            make_float2(acc[nb][0] + b0v, acc[nb][1] + b1v);
        *(float2*)&out[(size_t)(m0g + row0 + 8) * Dm + n] =
            make_float2(acc[nb][2] + b0v, acc[nb][3] + b1v);
    }
}

// ===========================================================================
// Flash attention, tf32 mma. 128 q-rows per CTA, 64-kv tiles, 8 warps.
// grid: (32, 16)  block 256
// smem: Ksh[64][68] | Vsh[64][72] | Psh[128][68]  (P area also stages Q)
// ===========================================================================
#define PK 68   // mod32 == 4
#define PV 72   // mod32 == 8
#define PP 68
#define ATT_SMEM_FLOATS (64 * PK + 64 * PV + 128 * PP)
#define ATT_SMEM_BYTES (ATT_SMEM_FLOATS * 4)

__global__ __launch_bounds__(256, 2)
void attn_kernel()
{
    extern __shared__ float sm[];
    float (*Ksh)[PK] = (float (*)[PK])sm;
    float (*Vsh)[PV] = (float (*)[PV])(sm + 64 * PK);
    float (*Psh)[PP] = (float (*)[PP])(sm + 64 * PK + 64 * PV);

    const int tid = threadIdx.x, lane = tid & 31, warp = tid >> 5;
    const int quad = lane >> 2, tg = lane & 3;
    const int row0 = warp * 16 + quad;      // rows row0 and row0+8 of 128-tile
    const int bh = blockIdx.y;

    const float* __restrict__ Qg = g_q + (size_t)bh * Sq * Hd + (size_t)blockIdx.x * 128 * Hd;
    const float* __restrict__ Kg = g_k + (size_t)bh * Sq * Hd;
    const float* __restrict__ Vg = g_v + (size_t)bh * Sq * Hd;

    // ---- Stage Q tile into Psh, then pull scaled tf32 fragments to regs ----
    #pragma unroll
    for (int i = 0; i < 8; i++) {
        int idx = tid + i * 256;           // 2048 float4
        int r = idx >> 4, cq = idx & 15;
        float4 v = *(const float4*)&Qg[(size_t)r * Hd + cq * 4];
        *(float4*)&Psh[r][cq * 4] = v;
    }
    __syncthreads();

    uint32_t qf[8][4];
    #pragma unroll
    for (int kc = 0; kc < 8; kc++) {
        qf[kc][0] = f2tf(Psh[row0    ][kc * 8 + tg    ] * INV_SQRT_D);
        qf[kc][1] = f2tf(Psh[row0 + 8][kc * 8 + tg    ] * INV_SQRT_D);
        qf[kc][2] = f2tf(Psh[row0    ][kc * 8 + tg + 4] * INV_SQRT_D);
        qf[kc][3] = f2tf(Psh[row0 + 8][kc * 8 + tg + 4] * INV_SQRT_D);
    }
    // (Psh reuse below is warp-local to each warp's own 16 rows — no hazard)

    float m0 = -INFINITY, m1 = -INFINITY, l0 = 0.0f, l1 = 0.0f;
    float o[8][4];
    #pragma unroll
    for (int nb = 0; nb < 8; nb++)
        #pragma unroll
        for (int j = 0; j < 4; j++) o[nb][j] = 0.0f;

    #pragma unroll 1
    for (int kt = 0; kt < Sq / 64; kt++) {
        const int kvbase = kt * 64;
        __syncthreads();   // protect K/V from previous iteration's consumers

        // load K,V tiles with tf32 conversion (1024 float4 each, 4/thread)
        #pragma unroll
        for (int i = 0; i < 4; i++) {
            int idx = tid + i * 256;
            int r = idx >> 4, cq = idx & 15;
            float4 v = *(const float4*)&Kg[(size_t)(kvbase + r) * Hd + cq * 4];
            float4 w;
            w.x = __uint_as_float(f2tf(v.x)); w.y = __uint_as_float(f2tf(v.y));
            w.z = __uint_as_float(f2tf(v.z)); w.w = __uint_as_float(f2tf(v.w));
            *(float4*)&Ksh[r][cq * 4] = w;
            float4 u = *(const float4*)&Vg[(size_t)(kvbase + r) * Hd + cq * 4];
            float4 t;
            t.x = __uint_as_float(f2tf(u.x)); t.y = __uint_as_float(f2tf(u.y));
            t.z = __uint_as_float(f2tf(u.z)); t.w = __uint_as_float(f2tf(u.w));
            *(float4*)&Vsh[r][cq * 4] = t;
        }
        __syncthreads();

        // ---- S = (Q*scale) @ K^T ----
        float s[8][4];
        #pragma unroll
        for (int nb = 0; nb < 8; nb++)
            #pragma unroll
            for (int j = 0; j < 4; j++) s[nb][j] = 0.0f;

        #pragma unroll
        for (int kc = 0; kc < 8; kc++) {
            #pragma unroll
            for (int nb = 0; nb < 8; nb++) {
                uint32_t b0 = ldsb(&Ksh[nb * 8 + quad][kc * 8 + tg]);
                uint32_t b1 = ldsb(&Ksh[nb * 8 + quad][kc * 8 + tg + 4]);
                mma_tf32(s[nb], qf[kc][0], qf[kc][1], qf[kc][2], qf[kc][3], b0, b1);
            }
        }

        // ---- online softmax (rows r0 = row0, r1 = row0+8) ----
        float rmax0 = -INFINITY, rmax1 = -INFINITY;
        #pragma unroll
        for (int nb = 0; nb < 8; nb++) {
            rmax0 = fmaxf(rmax0, fmaxf(s[nb][0], s[nb][1]));
            rmax1 = fmaxf(rmax1, fmaxf(s[nb][2], s[nb][3]));
        }
        rmax0 = fmaxf(rmax0, __shfl_xor_sync(0xffffffff, rmax0, 1));
        rmax0 = fmaxf(rmax0, __shfl_xor_sync(0xffffffff, rmax0, 2));
        rmax1 = fmaxf(rmax1, __shfl_xor_sync(0xffffffff, rmax1, 1));
        rmax1 = fmaxf(rmax1, __shfl_xor_sync(0xffffffff, rmax1, 2));

        float mn0 = fmaxf(m0, rmax0), mn1 = fmaxf(m1, rmax1);
        float al0 = __expf(m0 - mn0), al1 = __expf(m1 - mn1);
        m0 = mn0; m1 = mn1;

        float ps0 = 0.0f, ps1 = 0.0f;
        #pragma unroll
        for (int nb = 0; nb < 8; nb++) {
            s[nb][0] = __expf(s[nb][0] - m0);
            s[nb][1] = __expf(s[nb][1] - m0);
            s[nb][2] = __expf(s[nb][2] - m1);
            s[nb][3] = __expf(s[nb][3] - m1);
            ps0 += s[nb][0] + s[nb][1];
            ps1 += s[nb][2] + s[nb][3];
        }
        ps0 += __shfl_xor_sync(0xffffffff, ps0, 1);
        ps0 += __shfl_xor_sync(0xffffffff, ps0, 2);
        ps1 += __shfl_xor_sync(0xffffffff, ps1, 1);
        ps1 += __shfl_xor_sync(0xffffffff, ps1, 2);
        l0 = l0 * al0 + ps0;
        l1 = l1 * al1 + ps1;

        #pragma unroll
        for (int nb = 0; nb < 8; nb++) {
            o[nb][0] *= al0; o[nb][1] *= al0;
            o[nb][2] *= al1; o[nb][3] *= al1;
        }

        // ---- P -> smem (warp-local rows), tf32 ----
        #pragma unroll
        for (int nb = 0; nb < 8; nb++) {
            float2 p0 = make_float2(__uint_as_float(f2tf(s[nb][0])),
                                    __uint_as_float(f2tf(s[nb][1])));
            float2 p1 = make_float2(__uint_as_float(f2tf(s[nb][2])),
                                    __uint_as_float(f2tf(s[nb][3])));
            *(float2*)&Psh[row0    ][nb * 8 + 2 * tg] = p0;
            *(float2*)&Psh[row0 + 8][nb * 8 + 2 * tg] = p1;
        }
        __syncwarp();

        // ---- O += P @ V ----
        #pragma unroll
        for (int kc = 0; kc < 8; kc++) {
            uint32_t a0 = ldsb(&Psh[row0    ][kc * 8 + tg]);
            uint32_t a1 = ldsb(&Psh[row0 + 8][kc * 8 + tg]);
            uint32_t a2 = ldsb(&Psh[row0    ][kc * 8 + tg + 4]);
            uint32_t a3 = ldsb(&Psh[row0 + 8][kc * 8 + tg + 4]);
            #pragma unroll
            for (int nb = 0; nb < 8; nb++) {
                uint32_t b0 = ldsb(&Vsh[kc * 8 + tg    ][nb * 8 + quad]);
                uint32_t b1 = ldsb(&Vsh[kc * 8 + tg + 4][nb * 8 + quad]);
                mma_tf32(o[nb], a0, a1, a2, a3, b0, b1);
            }
        }
    }

    // ---- epilogue: O/l -> g_ctx [B*S, D] ----
    const int b = bh >> 3, h = bh & 7;
    const float inv0 = 1.0f / l0, inv1 = 1.0f / l1;
    const int s0 = blockIdx.x * 128 + row0;
    const int s1 = s0 + 8;
    #pragma unroll
    for (int nb = 0; nb < 8; nb++) {
        int d = nb * 8 + 2 * tg;
        *(float2*)&g_ctx[((size_t)(b * Sq + s0)) * Dm + h * Hd + d] =
            make_float2(o[nb][0] * inv0, o[nb][1] * inv0);
        *(float2*)&g_ctx[((size_t)(b * Sq + s1)) * Dm + h * Hd + d] =
            make_float2(o[nb][2] * inv1, o[nb][3] * inv1);
    }
}

// ---------------------------------------------------------------------------
extern "C" void kernel_launch(void* const* d_in, const int* in_sizes, int n_in,
                              void* d_out, int out_size)
{
    const float* x  = (const float*)d_in[0];
    const float* Wq = (const float*)d_in[1];
    const float* bq = (const float*)d_in[2];
    const float* Wk = (const float*)d_in[3];
    const float* bk = (const float*)d_in[4];
    const float* Wv = (const float*)d_in[5];
    const float* bv = (const float*)d_in[6];
    const float* Wo = (const float*)d_in[7];
    const float* bo = (const float*)d_in[8];
    float* out = (float*)d_out;

    cudaFuncSetAttribute(attn_kernel, cudaFuncAttributeMaxDynamicSharedMemorySize,
                         ATT_SMEM_BYTES);

    proj_qkv_kernel<<<dim3(Dm / 64, Mrows / 128, 3), 256>>>(x, Wq, bq, Wk, bk, Wv, bv);
    attn_kernel<<<dim3(Sq / 128, Bz * Hh), 256, ATT_SMEM_BYTES>>>();
    proj_out_kernel<<<dim3(Dm / 64, Mrows / 128), 256>>>(Wo, bo, out);
}

// round 4
// speedup vs baseline: 5.4853x; 1.6953x over previous
#include <cuda_runtime.h>
#include <cuda_fp16.h>
#include <math.h>
#include <stdint.h>

#define Bz 2
#define Sq 4096
#define Dm 512
#define Hh 8
#define Hd 64
#define Mrows (Bz*Sq)           // 8192
#define INV_SQRT_D 0.044194173824159216f   // 1/sqrt(512)

// Scratch (static device arrays — no cudaMalloc anywhere)
__device__ __half g_q[(size_t)Bz*Hh*Sq*Hd];   // [B,H,S,Hd], pre-scaled by 1/sqrt(D)
__device__ __half g_k[(size_t)Bz*Hh*Sq*Hd];
__device__ __half g_v[(size_t)Bz*Hh*Sq*Hd];
__device__ float  g_ctx[(size_t)Mrows*Dm];    // [B*S, D]

// ---------------------------------------------------------------------------
// helpers
// ---------------------------------------------------------------------------
__device__ __forceinline__ uint32_t f2tf(float x) {
    uint32_t t;
    asm("cvt.rna.tf32.f32 %0, %1;" : "=r"(t) : "f"(x));
    return t;
}

__device__ __forceinline__ void mma_tf32(float* c,
                                         uint32_t a0, uint32_t a1, uint32_t a2, uint32_t a3,
                                         uint32_t b0, uint32_t b1) {
    asm volatile(
        "mma.sync.aligned.m16n8k8.row.col.f32.tf32.tf32.f32 "
        "{%0,%1,%2,%3},{%4,%5,%6,%7},{%8,%9},{%0,%1,%2,%3};"
        : "+f"(c[0]), "+f"(c[1]), "+f"(c[2]), "+f"(c[3])
        : "r"(a0), "r"(a1), "r"(a2), "r"(a3), "r"(b0), "r"(b1));
}

__device__ __forceinline__ void mma_f16(float* c,
                                        uint32_t a0, uint32_t a1, uint32_t a2, uint32_t a3,
                                        uint32_t b0, uint32_t b1) {
    asm volatile(
        "mma.sync.aligned.m16n8k16.row.col.f32.f16.f16.f32 "
        "{%0,%1,%2,%3},{%4,%5,%6,%7},{%8,%9},{%0,%1,%2,%3};"
        : "+f"(c[0]), "+f"(c[1]), "+f"(c[2]), "+f"(c[3])
        : "r"(a0), "r"(a1), "r"(a2), "r"(a3), "r"(b0), "r"(b1));
}

__device__ __forceinline__ void ldsm_x4(uint32_t& r0, uint32_t& r1, uint32_t& r2, uint32_t& r3,
                                        const void* p) {
    uint32_t addr = (uint32_t)__cvta_generic_to_shared(p);
    asm volatile("ldmatrix.sync.aligned.m8n8.x4.shared.b16 {%0,%1,%2,%3},[%4];"
                 : "=r"(r0), "=r"(r1), "=r"(r2), "=r"(r3) : "r"(addr));
}

__device__ __forceinline__ void ldsm_x4_t(uint32_t& r0, uint32_t& r1, uint32_t& r2, uint32_t& r3,
                                          const void* p) {
    uint32_t addr = (uint32_t)__cvta_generic_to_shared(p);
    asm volatile("ldmatrix.sync.aligned.m8n8.x4.trans.shared.b16 {%0,%1,%2,%3},[%4];"
                 : "=r"(r0), "=r"(r1), "=r"(r2), "=r"(r3) : "r"(addr));
}

__device__ __forceinline__ void cp_async16(void* smem, const void* gmem) {
    uint32_t s = (uint32_t)__cvta_generic_to_shared(smem);
    asm volatile("cp.async.cg.shared.global [%0], [%1], 16;" :: "r"(s), "l"(gmem));
}
__device__ __forceinline__ void cp_commit() { asm volatile("cp.async.commit_group;"); }
template<int N> __device__ __forceinline__ void cp_wait() {
    asm volatile("cp.async.wait_group %0;" :: "n"(N));
}

__device__ __forceinline__ uint32_t ldsb(const float* p) { return __float_as_uint(*p); }
__device__ __forceinline__ uint32_t packh2(float x, float y) {
    __half2 h = __floats2half2_rn(x, y);
    return *(uint32_t*)&h;
}

// ===========================================================================
// QKV projection GEMM (tf32 mma): out = x @ W + b, fp16 output in [B,H,S,Hd]
// Q additionally pre-scaled by 1/sqrt(D).
// tile 128x64, K chunk 32, 256 threads. grid: (8, 64, 3)
// ===========================================================================
#define PA 36
#define PW 72

__global__ __launch_bounds__(256, 2)
void proj_qkv_kernel(const float* __restrict__ x,
                     const float* __restrict__ Wq, const float* __restrict__ bq,
                     const float* __restrict__ Wk, const float* __restrict__ bk,
                     const float* __restrict__ Wv, const float* __restrict__ bv)
{
    const int which = blockIdx.z;
    const float* __restrict__ W    = (which == 0) ? Wq : (which == 1) ? Wk : Wv;
    const float* __restrict__ bias = (which == 0) ? bq : (which == 1) ? bk : bv;
    __half* __restrict__ out       = (which == 0) ? g_q : (which == 1) ? g_k : g_v;
    const float oscale = (which == 0) ? INV_SQRT_D : 1.0f;

    __shared__ float Ash[128][PA];
    __shared__ float Wsh[32][PW];

    const int tid = threadIdx.x, lane = tid & 31, warp = tid >> 5;
    const int quad = lane >> 2, tg = lane & 3;
    const int row0 = warp * 16 + quad;
    const int m0g  = blockIdx.y * 128;
    const int col0 = blockIdx.x * 64;

    float acc[8][4];
    #pragma unroll
    for (int nb = 0; nb < 8; nb++)
        #pragma unroll
        for (int j = 0; j < 4; j++) acc[nb][j] = 0.0f;

    for (int k0 = 0; k0 < Dm; k0 += 32) {
        #pragma unroll
        for (int i = 0; i < 4; i++) {
            int idx = tid + i * 256;
            int r = idx >> 3, cq = idx & 7;
            float4 v = *(const float4*)&x[(size_t)(m0g + r) * Dm + k0 + cq * 4];
            float4 w;
            w.x = __uint_as_float(f2tf(v.x)); w.y = __uint_as_float(f2tf(v.y));
            w.z = __uint_as_float(f2tf(v.z)); w.w = __uint_as_float(f2tf(v.w));
            *(float4*)&Ash[r][cq * 4] = w;
        }
        #pragma unroll
        for (int i = 0; i < 2; i++) {
            int idx = tid + i * 256;
            int r = idx >> 4, cq = idx & 15;
            float4 v = *(const float4*)&W[(size_t)(k0 + r) * Dm + col0 + cq * 4];
            float4 w;
            w.x = __uint_as_float(f2tf(v.x)); w.y = __uint_as_float(f2tf(v.y));
            w.z = __uint_as_float(f2tf(v.z)); w.w = __uint_as_float(f2tf(v.w));
            *(float4*)&Wsh[r][cq * 4] = w;
        }
        __syncthreads();

        #pragma unroll
        for (int kc = 0; kc < 4; kc++) {
            uint32_t a0 = ldsb(&Ash[row0    ][kc * 8 + tg]);
            uint32_t a1 = ldsb(&Ash[row0 + 8][kc * 8 + tg]);
            uint32_t a2 = ldsb(&Ash[row0    ][kc * 8 + tg + 4]);
            uint32_t a3 = ldsb(&Ash[row0 + 8][kc * 8 + tg + 4]);
            #pragma unroll
            for (int nb = 0; nb < 8; nb++) {
                uint32_t b0 = ldsb(&Wsh[kc * 8 + tg    ][nb * 8 + quad]);
                uint32_t b1 = ldsb(&Wsh[kc * 8 + tg + 4][nb * 8 + quad]);
                mma_tf32(acc[nb], a0, a1, a2, a3, b0, b1);
            }
        }
        __syncthreads();
    }

    const int h = blockIdx.x;   // 64-wide tile == one head
    #pragma unroll
    for (int nb = 0; nb < 8; nb++) {
        int d = nb * 8 + 2 * tg;
        float b0v = bias[col0 + d], b1v = bias[col0 + d + 1];
        int m = m0g + row0;
        int b = m >> 12, s = m & 4095;
        *(uint32_t*)&out[(((size_t)(b * Hh + h) * Sq) + s) * Hd + d] =
            packh2((acc[nb][0] + b0v) * oscale, (acc[nb][1] + b1v) * oscale);
        m = m0g + row0 + 8;
        b = m >> 12; s = m & 4095;
        *(uint32_t*)&out[(((size_t)(b * Hh + h) * Sq) + s) * Hd + d] =
            packh2((acc[nb][2] + b0v) * oscale, (acc[nb][3] + b1v) * oscale);
    }
}

// ===========================================================================
// Output projection GEMM (tf32 mma): d_out = g_ctx @ Wo + bo
// ===========================================================================
__global__ __launch_bounds__(256, 2)
void proj_out_kernel(const float* __restrict__ Wo,
                     const float* __restrict__ bo,
                     float* __restrict__ out)
{
    __shared__ float Ash[128][PA];
    __shared__ float Wsh[32][PW];

    const int tid = threadIdx.x, lane = tid & 31, warp = tid >> 5;
    const int quad = lane >> 2, tg = lane & 3;
    const int row0 = warp * 16 + quad;
    const int m0g  = blockIdx.y * 128;
    const int col0 = blockIdx.x * 64;

    float acc[8][4];
    #pragma unroll
    for (int nb = 0; nb < 8; nb++)
        #pragma unroll
        for (int j = 0; j < 4; j++) acc[nb][j] = 0.0f;

    for (int k0 = 0; k0 < Dm; k0 += 32) {
        #pragma unroll
        for (int i = 0; i < 4; i++) {
            int idx = tid + i * 256;
            int r = idx >> 3, cq = idx & 7;
            float4 v = *(const float4*)&g_ctx[(size_t)(m0g + r) * Dm + k0 + cq * 4];
            float4 w;
            w.x = __uint_as_float(f2tf(v.x)); w.y = __uint_as_float(f2tf(v.y));
            w.z = __uint_as_float(f2tf(v.z)); w.w = __uint_as_float(f2tf(v.w));
            *(float4*)&Ash[r][cq * 4] = w;
        }
        #pragma unroll
        for (int i = 0; i < 2; i++) {
            int idx = tid + i * 256;
            int r = idx >> 4, cq = idx & 15;
            float4 v = *(const float4*)&Wo[(size_t)(k0 + r) * Dm + col0 + cq * 4];
            float4 w;
            w.x = __uint_as_float(f2tf(v.x)); w.y = __uint_as_float(f2tf(v.y));
            w.z = __uint_as_float(f2tf(v.z)); w.w = __uint_as_float(f2tf(v.w));
            *(float4*)&Wsh[r][cq * 4] = w;
        }
        __syncthreads();

        #pragma unroll
        for (int kc = 0; kc < 4; kc++) {
            uint32_t a0 = ldsb(&Ash[row0    ][kc * 8 + tg]);
            uint32_t a1 = ldsb(&Ash[row0 + 8][kc * 8 + tg]);
            uint32_t a2 = ldsb(&Ash[row0    ][kc * 8 + tg + 4]);
            uint32_t a3 = ldsb(&Ash[row0 + 8][kc * 8 + tg + 4]);
            #pragma unroll
            for (int nb = 0; nb < 8; nb++) {
                uint32_t b0 = ldsb(&Wsh[kc * 8 + tg    ][nb * 8 + quad]);
                uint32_t b1 = ldsb(&Wsh[kc * 8 + tg + 4][nb * 8 + quad]);
                mma_tf32(acc[nb], a0, a1, a2, a3, b0, b1);
            }
        }
        __syncthreads();
    }

    #pragma unroll
    for (int nb = 0; nb < 8; nb++) {
        int n = col0 + nb * 8 + 2 * tg;
        float b0v = bo[n], b1v = bo[n + 1];
        *(float2*)&out[(size_t)(m0g + row0) * Dm + n] =
            make_float2(acc[nb][0] + b0v, acc[nb][1] + b1v);
        *(float2*)&out[(size_t)(m0g + row0 + 8) * Dm + n] =
            make_float2(acc[nb][2] + b0v, acc[nb][3] + b1v);
    }
}

// ===========================================================================
// Flash attention, fp16 m16n8k16 mma, fp32 accum.
// 128 q-rows per CTA, 64-kv tiles, 8 warps, cp.async double buffering.
// grid: (32, 16)  block 256
// smem: 2 x { Ksh[64][72] fp16, Vsh[64][72] fp16 }  = 36864 B
// ===========================================================================
#define KVP 72                        // pitch in halves (144 B rows: conflict-free LDSM)
#define KVBUF (64 * KVP)              // halves per K (or V) buffer
#define ATT_SMEM_BYTES (4 * KVBUF * 2)

__global__ __launch_bounds__(256, 2)
void attn_kernel()
{
    extern __shared__ __align__(16) __half sm[];
    // buffers: [buf] K at sm + buf*2*KVBUF, V at +KVBUF
    const int tid = threadIdx.x, lane = tid & 31, warp = tid >> 5;
    const int quad = lane >> 2, tg = lane & 3;
    const int m8 = lane >> 3;     // which 8x8 matrix for ldmatrix (0..3)
    const int r8 = lane & 7;      // row within matrix
    const int bh = blockIdx.y;

    const __half* __restrict__ Qg = g_q + (size_t)bh * Sq * Hd + (size_t)blockIdx.x * 128 * Hd;
    const __half* __restrict__ Kg = g_k + (size_t)bh * Sq * Hd;
    const __half* __restrict__ Vg = g_v + (size_t)bh * Sq * Hd;

    // ---- Stage Q tile (128x64 fp16) into smem, pull A fragments to regs ----
    {
        __half* Qs = sm;   // pitch KVP
        #pragma unroll
        for (int i = 0; i < 4; i++) {
            int idx = tid + i * 256;      // 1024 float4 (8 halves each)
            int r = idx >> 3, cq = idx & 7;
            *(float4*)&Qs[r * KVP + cq * 8] = *(const float4*)&Qg[(size_t)r * Hd + cq * 8];
        }
        __syncthreads();
    }

    uint32_t qa[4][4];   // 4 k16-blocks x 4 A regs
    {
        const __half* Qs = sm;
        #pragma unroll
        for (int kc = 0; kc < 4; kc++) {
            const __half* p = &Qs[(warp * 16 + (m8 & 1) * 8 + r8) * KVP + kc * 16 + (m8 >> 1) * 8];
            ldsm_x4(qa[kc][0], qa[kc][1], qa[kc][2], qa[kc][3], p);
        }
        __syncthreads();   // done with Q staging area before K/V prefetch
    }

    float m0 = -INFINITY, m1 = -INFINITY, l0 = 0.0f, l1 = 0.0f;
    float o[8][4];
    #pragma unroll
    for (int nb = 0; nb < 8; nb++)
        #pragma unroll
        for (int j = 0; j < 4; j++) o[nb][j] = 0.0f;

    // prefetch tile 0 into buffer 0
    {
        __half* Ks = sm;            // buf0 K
        __half* Vs = sm + KVBUF;    // buf0 V
        #pragma unroll
        for (int i = 0; i < 2; i++) {
            int idx = tid + i * 256;      // 512 float4 per array
            int r = idx >> 3, cq = idx & 7;
            cp_async16(&Ks[r * KVP + cq * 8], &Kg[(size_t)r * Hd + cq * 8]);
            cp_async16(&Vs[r * KVP + cq * 8], &Vg[(size_t)r * Hd + cq * 8]);
        }
        cp_commit();
    }

    #pragma unroll 1
    for (int kt = 0; kt < Sq / 64; kt++) {
        const int cur = kt & 1;
        // prefetch next tile
        if (kt + 1 < Sq / 64) {
            const int nxt = cur ^ 1;
            __half* Ks = sm + nxt * 2 * KVBUF;
            __half* Vs = Ks + KVBUF;
            const size_t base = (size_t)(kt + 1) * 64;
            #pragma unroll
            for (int i = 0; i < 2; i++) {
                int idx = tid + i * 256;
                int r = idx >> 3, cq = idx & 7;
                cp_async16(&Ks[r * KVP + cq * 8], &Kg[(base + r) * Hd + cq * 8]);
                cp_async16(&Vs[r * KVP + cq * 8], &Vg[(base + r) * Hd + cq * 8]);
            }
            cp_commit();
            cp_wait<1>();
        } else {
            cp_wait<0>();
        }
        __syncthreads();    // current buffer visible to all warps

        const __half* Ks = sm + cur * 2 * KVBUF;
        const __half* Vs = Ks + KVBUF;

        // ---- S = Qs @ K^T  (Q pre-scaled) ----
        float s[8][4];
        #pragma unroll
        for (int nb = 0; nb < 8; nb++)
            #pragma unroll
            for (int j = 0; j < 4; j++) s[nb][j] = 0.0f;

        #pragma unroll
        for (int nb = 0; nb < 8; nb++) {
            #pragma unroll
            for (int kcp = 0; kcp < 2; kcp++) {
                uint32_t b0, b1, b2, b3;
                // matrices: tokens nb*8+r8 ; d = kcp*32 + m8*8
                const __half* p = &Ks[(nb * 8 + r8) * KVP + kcp * 32 + m8 * 8];
                ldsm_x4(b0, b1, b2, b3, p);
                mma_f16(s[nb], qa[kcp * 2][0], qa[kcp * 2][1], qa[kcp * 2][2], qa[kcp * 2][3], b0, b1);
                mma_f16(s[nb], qa[kcp * 2 + 1][0], qa[kcp * 2 + 1][1], qa[kcp * 2 + 1][2], qa[kcp * 2 + 1][3], b2, b3);
            }
        }

        // ---- online softmax (rows row0=warp*16+quad, row0+8) ----
        float rmax0 = -INFINITY, rmax1 = -INFINITY;
        #pragma unroll
        for (int nb = 0; nb < 8; nb++) {
            rmax0 = fmaxf(rmax0, fmaxf(s[nb][0], s[nb][1]));
            rmax1 = fmaxf(rmax1, fmaxf(s[nb][2], s[nb][3]));
        }
        rmax0 = fmaxf(rmax0, __shfl_xor_sync(0xffffffff, rmax0, 1));
        rmax0 = fmaxf(rmax0, __shfl_xor_sync(0xffffffff, rmax0, 2));
        rmax1 = fmaxf(rmax1, __shfl_xor_sync(0xffffffff, rmax1, 1));
        rmax1 = fmaxf(rmax1, __shfl_xor_sync(0xffffffff, rmax1, 2));

        float mn0 = fmaxf(m0, rmax0), mn1 = fmaxf(m1, rmax1);
        float al0 = __expf(m0 - mn0), al1 = __expf(m1 - mn1);
        m0 = mn0; m1 = mn1;

        float ps0 = 0.0f, ps1 = 0.0f;
        #pragma unroll
        for (int nb = 0; nb < 8; nb++) {
            s[nb][0] = __expf(s[nb][0] - m0);
            s[nb][1] = __expf(s[nb][1] - m0);
            s[nb][2] = __expf(s[nb][2] - m1);
            s[nb][3] = __expf(s[nb][3] - m1);
            ps0 += s[nb][0] + s[nb][1];
            ps1 += s[nb][2] + s[nb][3];
        }
        ps0 += __shfl_xor_sync(0xffffffff, ps0, 1);
        ps0 += __shfl_xor_sync(0xffffffff, ps0, 2);
        ps1 += __shfl_xor_sync(0xffffffff, ps1, 1);
        ps1 += __shfl_xor_sync(0xffffffff, ps1, 2);
        l0 = l0 * al0 + ps0;
        l1 = l1 * al1 + ps1;

        #pragma unroll
        for (int nb = 0; nb < 8; nb++) {
            o[nb][0] *= al0; o[nb][1] *= al0;
            o[nb][2] *= al1; o[nb][3] *= al1;
        }

        // ---- P fragments straight from accumulators (no smem) ----
        uint32_t pa[4][4];
        #pragma unroll
        for (int j = 0; j < 4; j++) {
            pa[j][0] = packh2(s[2 * j    ][0], s[2 * j    ][1]);
            pa[j][1] = packh2(s[2 * j    ][2], s[2 * j    ][3]);
            pa[j][2] = packh2(s[2 * j + 1][0], s[2 * j + 1][1]);
            pa[j][3] = packh2(s[2 * j + 1][2], s[2 * j + 1][3]);
        }

        // ---- O += P @ V  (V via ldmatrix.trans) ----
        #pragma unroll
        for (int nb = 0; nb < 8; nb++) {
            #pragma unroll
            for (int kcp = 0; kcp < 2; kcp++) {
                uint32_t b0, b1, b2, b3;
                // matrices: tokens kcp*32 + m8*8 + r8 ; d = nb*8
                const __half* p = &Vs[(kcp * 32 + m8 * 8 + r8) * KVP + nb * 8];
                ldsm_x4_t(b0, b1, b2, b3, p);
                mma_f16(o[nb], pa[kcp * 2][0], pa[kcp * 2][1], pa[kcp * 2][2], pa[kcp * 2][3], b0, b1);
                mma_f16(o[nb], pa[kcp * 2 + 1][0], pa[kcp * 2 + 1][1], pa[kcp * 2 + 1][2], pa[kcp * 2 + 1][3], b2, b3);
            }
        }
        __syncthreads();   // all warps done with cur buffer before next prefetch overwrites
    }

    // ---- epilogue: O/l -> g_ctx [B*S, D] ----
    const int b = bh >> 3, h = bh & 7;
    const int row0 = warp * 16 + quad;
    const float inv0 = 1.0f / l0, inv1 = 1.0f / l1;
    const int s0 = blockIdx.x * 128 + row0;
    const int s1 = s0 + 8;
    #pragma unroll
    for (int nb = 0; nb < 8; nb++) {
        int d = nb * 8 + 2 * tg;
        *(float2*)&g_ctx[((size_t)(b * Sq + s0)) * Dm + h * Hd + d] =
            make_float2(o[nb][0] * inv0, o[nb][1] * inv0);
        *(float2*)&g_ctx[((size_t)(b * Sq + s1)) * Dm + h * Hd + d] =
            make_float2(o[nb][2] * inv1, o[nb][3] * inv1);
    }
}

// ---------------------------------------------------------------------------
extern "C" void kernel_launch(void* const* d_in, const int* in_sizes, int n_in,
                              void* d_out, int out_size)
{
    const float* x  = (const float*)d_in[0];
    const float* Wq = (const float*)d_in[1];
    const float* bq = (const float*)d_in[2];
    const float* Wk = (const float*)d_in[3];
    const float* bk = (const float*)d_in[4];
    const float* Wv = (const float*)d_in[5];
    const float* bv = (const float*)d_in[6];
    const float* Wo = (const float*)d_in[7];
    const float* bo = (const float*)d_in[8];
    float* out = (float*)d_out;

    cudaFuncSetAttribute(attn_kernel, cudaFuncAttributeMaxDynamicSharedMemorySize,
                         ATT_SMEM_BYTES);

    proj_qkv_kernel<<<dim3(Dm / 64, Mrows / 128, 3), 256>>>(x, Wq, bq, Wk, bk, Wv, bv);
    attn_kernel<<<dim3(Sq / 128, Bz * Hh), 256, ATT_SMEM_BYTES>>>();
    proj_out_kernel<<<dim3(Dm / 64, Mrows / 128), 256>>>(Wo, bo, out);
}

// round 5
// speedup vs baseline: 7.3638x; 1.3425x over previous
#include <cuda_runtime.h>
#include <cuda_fp16.h>
#include <math.h>
#include <stdint.h>

#define Bz 2
#define Sq 4096
#define Dm 512
#define Hh 8
#define Hd 64
#define Mrows (Bz*Sq)           // 8192
#define DmDm (Dm*Dm)
#define INV_SQRT_D 0.044194173824159216f   // 1/sqrt(512)
#define LOG2E_F 1.4426950408889634f
#define ONES_H2 0x3C003C00u

// Scratch (static device arrays — no cudaMalloc anywhere)
__device__ __half g_xh[(size_t)Mrows*Dm];     // x in fp16
__device__ __half g_w4[(size_t)4*DmDm];       // Wq,Wk,Wv,Wo in fp16 [in][out]
__device__ __half g_q[(size_t)Bz*Hh*Sq*Hd];   // [B,H,S,Hd], pre-scaled by 1/sqrt(D)
__device__ __half g_k[(size_t)Bz*Hh*Sq*Hd];
__device__ __half g_v[(size_t)Bz*Hh*Sq*Hd];
__device__ __half g_ctx[(size_t)Mrows*Dm];    // [B*S, D] fp16

// ---------------------------------------------------------------------------
// helpers
// ---------------------------------------------------------------------------
__device__ __forceinline__ void mma_f16(float* c,
                                        uint32_t a0, uint32_t a1, uint32_t a2, uint32_t a3,
                                        uint32_t b0, uint32_t b1) {
    asm volatile(
        "mma.sync.aligned.m16n8k16.row.col.f32.f16.f16.f32 "
        "{%0,%1,%2,%3},{%4,%5,%6,%7},{%8,%9},{%0,%1,%2,%3};"
        : "+f"(c[0]), "+f"(c[1]), "+f"(c[2]), "+f"(c[3])
        : "r"(a0), "r"(a1), "r"(a2), "r"(a3), "r"(b0), "r"(b1));
}

__device__ __forceinline__ void ldsm_x4(uint32_t& r0, uint32_t& r1, uint32_t& r2, uint32_t& r3,
                                        const void* p) {
    uint32_t addr = (uint32_t)__cvta_generic_to_shared(p);
    asm volatile("ldmatrix.sync.aligned.m8n8.x4.shared.b16 {%0,%1,%2,%3},[%4];"
                 : "=r"(r0), "=r"(r1), "=r"(r2), "=r"(r3) : "r"(addr));
}

__device__ __forceinline__ void ldsm_x4_t(uint32_t& r0, uint32_t& r1, uint32_t& r2, uint32_t& r3,
                                          const void* p) {
    uint32_t addr = (uint32_t)__cvta_generic_to_shared(p);
    asm volatile("ldmatrix.sync.aligned.m8n8.x4.trans.shared.b16 {%0,%1,%2,%3},[%4];"
                 : "=r"(r0), "=r"(r1), "=r"(r2), "=r"(r3) : "r"(addr));
}

__device__ __forceinline__ void cp_async16(void* smem, const void* gmem) {
    uint32_t s = (uint32_t)__cvta_generic_to_shared(smem);
    asm volatile("cp.async.cg.shared.global [%0], [%1], 16;" :: "r"(s), "l"(gmem));
}
__device__ __forceinline__ void cp_commit() { asm volatile("cp.async.commit_group;"); }
template<int N> __device__ __forceinline__ void cp_wait() {
    asm volatile("cp.async.wait_group %0;" :: "n"(N));
}

__device__ __forceinline__ uint32_t packh2(float lo, float hi) {
    uint32_t r;
    asm("cvt.rn.f16x2.f32 %0, %1, %2;" : "=r"(r) : "f"(hi), "f"(lo));
    return r;
}
__device__ __forceinline__ uint32_t ex2h2(uint32_t x) {
    uint32_t r;
    asm("ex2.approx.f16x2 %0, %1;" : "=r"(r) : "r"(x));
    return r;
}

// ===========================================================================
// fp16 pre-conversion kernels
// ===========================================================================
__global__ void cvt_x_kernel(const float* __restrict__ x)
{
    size_t i = ((size_t)blockIdx.x * 256 + threadIdx.x) * 4;
    float4 v = *(const float4*)&x[i];
    uint2 d;
    d.x = packh2(v.x, v.y);
    d.y = packh2(v.z, v.w);
    *(uint2*)&g_xh[i] = d;
}

__global__ void cvt_w_kernel(const float* __restrict__ Wq, const float* __restrict__ Wk,
                             const float* __restrict__ Wv, const float* __restrict__ Wo)
{
    // 256 blocks per matrix, 4 elems per thread
    int which = blockIdx.x >> 8;
    const float* src = (which == 0) ? Wq : (which == 1) ? Wk : (which == 2) ? Wv : Wo;
    size_t i = ((size_t)(blockIdx.x & 255) * 256 + threadIdx.x) * 4;
    float4 v = *(const float4*)&src[i];
    uint2 d;
    d.x = packh2(v.x, v.y);
    d.y = packh2(v.z, v.w);
    *(uint2*)&g_w4[(size_t)which * DmDm + i] = d;
}

// ===========================================================================
// fp16 projection GEMMs: tile 128(M) x 64(N), K chunk 64, double-buffered.
// 256 threads = 8 warps x 16 rows. A [row][k] pitch 72, W [k][n] pitch 72.
// smem: 2 stages x (128*72 + 64*72) halves = 55296 B
// ===========================================================================
#define PPITCH 72
#define PA_H (128 * PPITCH)
#define PW_H (64 * PPITCH)
#define PSTAGE (PA_H + PW_H)
#define PROJ_SMEM_BYTES (2 * PSTAGE * 2)

__device__ __forceinline__ void proj_load_stage(__half* st, const __half* __restrict__ A,
                                                const __half* __restrict__ W,
                                                int m0g, int col0, int k0, int tid)
{
    __half* As = st;
    __half* Ws = st + PA_H;
    #pragma unroll
    for (int i = 0; i < 4; i++) {
        int idx = tid + i * 256;          // 1024 x 16B
        int r = idx >> 3, cq = idx & 7;
        cp_async16(&As[r * PPITCH + cq * 8], &A[(size_t)(m0g + r) * Dm + k0 + cq * 8]);
    }
    #pragma unroll
    for (int i = 0; i < 2; i++) {
        int idx = tid + i * 256;          // 512 x 16B
        int r = idx >> 3, cq = idx & 7;
        cp_async16(&Ws[r * PPITCH + cq * 8], &W[(size_t)(k0 + r) * Dm + col0 + cq * 8]);
    }
}

__device__ __forceinline__ void proj_compute_stage(const __half* st, float acc[8][4],
                                                   int warp, int m8, int r8)
{
    const __half* As = st;
    const __half* Ws = st + PA_H;
    uint32_t qa[4][4];
    #pragma unroll
    for (int kc = 0; kc < 4; kc++) {
        const __half* p = &As[(warp * 16 + (m8 & 1) * 8 + r8) * PPITCH + kc * 16 + (m8 >> 1) * 8];
        ldsm_x4(qa[kc][0], qa[kc][1], qa[kc][2], qa[kc][3], p);
    }
    #pragma unroll
    for (int kc2 = 0; kc2 < 2; kc2++) {
        #pragma unroll
        for (int nb = 0; nb < 8; nb++) {
            uint32_t b0, b1, b2, b3;
            const __half* p = &Ws[(kc2 * 32 + m8 * 8 + r8) * PPITCH + nb * 8];
            ldsm_x4_t(b0, b1, b2, b3, p);
            mma_f16(acc[nb], qa[kc2 * 2][0], qa[kc2 * 2][1], qa[kc2 * 2][2], qa[kc2 * 2][3], b0, b1);
            mma_f16(acc[nb], qa[kc2 * 2 + 1][0], qa[kc2 * 2 + 1][1], qa[kc2 * 2 + 1][2], qa[kc2 * 2 + 1][3], b2, b3);
        }
    }
}

// QKV projection: grid (8, 64, 3)
__global__ __launch_bounds__(256, 2)
void proj_qkv_kernel(const float* __restrict__ bq, const float* __restrict__ bk,
                     const float* __restrict__ bv)
{
    extern __shared__ __align__(16) __half psm[];
    const int which = blockIdx.z;
    const __half* __restrict__ W = g_w4 + (size_t)which * DmDm;
    const float* __restrict__ bias = (which == 0) ? bq : (which == 1) ? bk : bv;
    __half* __restrict__ out = (which == 0) ? g_q : (which == 1) ? g_k : g_v;
    const float oscale = (which == 0) ? INV_SQRT_D : 1.0f;

    const int tid = threadIdx.x, lane = tid & 31, warp = tid >> 5;
    const int quad = lane >> 2, tg = lane & 3;
    const int m8 = lane >> 3, r8 = lane & 7;
    const int m0g = blockIdx.y * 128;
    const int col0 = blockIdx.x * 64;

    float acc[8][4];
    #pragma unroll
    for (int nb = 0; nb < 8; nb++)
        #pragma unroll
        for (int j = 0; j < 4; j++) acc[nb][j] = 0.0f;

    proj_load_stage(psm, g_xh, W, m0g, col0, 0, tid);
    cp_commit();

    #pragma unroll 1
    for (int it = 0; it < Dm / 64; it++) {
        if (it + 1 < Dm / 64) {
            proj_load_stage(psm + ((it + 1) & 1) * PSTAGE, g_xh, W, m0g, col0, (it + 1) * 64, tid);
            cp_commit();
            cp_wait<1>();
        } else {
            cp_wait<0>();
        }
        __syncthreads();
        proj_compute_stage(psm + (it & 1) * PSTAGE, acc, warp, m8, r8);
        __syncthreads();
    }

    const int row0 = warp * 16 + quad;
    const int h = blockIdx.x;   // 64-wide tile == one head
    #pragma unroll
    for (int nb = 0; nb < 8; nb++) {
        int d = nb * 8 + 2 * tg;
        float b0v = bias[col0 + d], b1v = bias[col0 + d + 1];
        int m = m0g + row0;
        int b = m >> 12, s = m & 4095;
        *(uint32_t*)&out[(((size_t)(b * Hh + h) * Sq) + s) * Hd + d] =
            packh2((acc[nb][0] + b0v) * oscale, (acc[nb][1] + b1v) * oscale);
        m = m0g + row0 + 8;
        b = m >> 12; s = m & 4095;
        *(uint32_t*)&out[(((size_t)(b * Hh + h) * Sq) + s) * Hd + d] =
            packh2((acc[nb][2] + b0v) * oscale, (acc[nb][3] + b1v) * oscale);
    }
}

// Output projection: grid (8, 64), fp32 out
__global__ __launch_bounds__(256, 2)
void proj_out_kernel(const float* __restrict__ bo, float* __restrict__ out)
{
    extern __shared__ __align__(16) __half psm[];
    const __half* __restrict__ W = g_w4 + (size_t)3 * DmDm;

    const int tid = threadIdx.x, lane = tid & 31, warp = tid >> 5;
    const int quad = lane >> 2, tg = lane & 3;
    const int m8 = lane >> 3, r8 = lane & 7;
    const int m0g = blockIdx.y * 128;
    const int col0 = blockIdx.x * 64;

    float acc[8][4];
    #pragma unroll
    for (int nb = 0; nb < 8; nb++)
        #pragma unroll
        for (int j = 0; j < 4; j++) acc[nb][j] = 0.0f;

    proj_load_stage(psm, g_ctx, W, m0g, col0, 0, tid);
    cp_commit();

    #pragma unroll 1
    for (int it = 0; it < Dm / 64; it++) {
        if (it + 1 < Dm / 64) {
            proj_load_stage(psm + ((it + 1) & 1) * PSTAGE, g_ctx, W, m0g, col0, (it + 1) * 64, tid);
            cp_commit();
            cp_wait<1>();
        } else {
            cp_wait<0>();
        }
        __syncthreads();
        proj_compute_stage(psm + (it & 1) * PSTAGE, acc, warp, m8, r8);
        __syncthreads();
    }

    const int row0 = warp * 16 + quad;
    #pragma unroll
    for (int nb = 0; nb < 8; nb++) {
        int n = col0 + nb * 8 + 2 * tg;
        float b0v = bo[n], b1v = bo[n + 1];
        *(float2*)&out[(size_t)(m0g + row0) * Dm + n] =
            make_float2(acc[nb][0] + b0v, acc[nb][1] + b1v);
        *(float2*)&out[(size_t)(m0g + row0 + 8) * Dm + n] =
            make_float2(acc[nb][2] + b0v, acc[nb][3] + b1v);
    }
}

// ===========================================================================
// Flash attention, fp16 m16n8k16 mma, fp32 accum, f16x2 exp, l via ones-mma.
// 128 q-rows per CTA, 64-kv tiles, 8 warps, cp.async double buffering.
// grid: (32, 16)  block 256
// ===========================================================================
#define KVP 72
#define KVBUF (64 * KVP)
#define ATT_SMEM_BYTES (4 * KVBUF * 2)

__global__ __launch_bounds__(256, 2)
void attn_kernel()
{
    extern __shared__ __align__(16) __half sm[];
    const int tid = threadIdx.x, lane = tid & 31, warp = tid >> 5;
    const int quad = lane >> 2, tg = lane & 3;
    const int m8 = lane >> 3;
    const int r8 = lane & 7;
    const int bh = blockIdx.y;

    const __half* __restrict__ Qg = g_q + (size_t)bh * Sq * Hd + (size_t)blockIdx.x * 128 * Hd;
    const __half* __restrict__ Kg = g_k + (size_t)bh * Sq * Hd;
    const __half* __restrict__ Vg = g_v + (size_t)bh * Sq * Hd;

    // ---- Stage Q tile (128x64 fp16) into smem, pull A fragments to regs ----
    {
        __half* Qs = sm;
        #pragma unroll
        for (int i = 0; i < 4; i++) {
            int idx = tid + i * 256;
            int r = idx >> 3, cq = idx & 7;
            *(float4*)&Qs[r * KVP + cq * 8] = *(const float4*)&Qg[(size_t)r * Hd + cq * 8];
        }
        __syncthreads();
    }

    uint32_t qa[4][4];
    {
        const __half* Qs = sm;
        #pragma unroll
        for (int kc = 0; kc < 4; kc++) {
            const __half* p = &Qs[(warp * 16 + (m8 & 1) * 8 + r8) * KVP + kc * 16 + (m8 >> 1) * 8];
            ldsm_x4(qa[kc][0], qa[kc][1], qa[kc][2], qa[kc][3], p);
        }
        __syncthreads();
    }

    float m0 = -INFINITY, m1 = -INFINITY;
    float lacc[4] = {0.0f, 0.0f, 0.0f, 0.0f};
    float o[8][4];
    #pragma unroll
    for (int nb = 0; nb < 8; nb++)
        #pragma unroll
        for (int j = 0; j < 4; j++) o[nb][j] = 0.0f;

    // prefetch tile 0
    {
        __half* Ks = sm;
        __half* Vs = sm + KVBUF;
        #pragma unroll
        for (int i = 0; i < 2; i++) {
            int idx = tid + i * 256;
            int r = idx >> 3, cq = idx & 7;
            cp_async16(&Ks[r * KVP + cq * 8], &Kg[(size_t)r * Hd + cq * 8]);
            cp_async16(&Vs[r * KVP + cq * 8], &Vg[(size_t)r * Hd + cq * 8]);
        }
        cp_commit();
    }

    #pragma unroll 1
    for (int kt = 0; kt < Sq / 64; kt++) {
        const int cur = kt & 1;
        if (kt + 1 < Sq / 64) {
            const int nxt = cur ^ 1;
            __half* Ks = sm + nxt * 2 * KVBUF;
            __half* Vs = Ks + KVBUF;
            const size_t base = (size_t)(kt + 1) * 64;
            #pragma unroll
            for (int i = 0; i < 2; i++) {
                int idx = tid + i * 256;
                int r = idx >> 3, cq = idx & 7;
                cp_async16(&Ks[r * KVP + cq * 8], &Kg[(base + r) * Hd + cq * 8]);
                cp_async16(&Vs[r * KVP + cq * 8], &Vg[(base + r) * Hd + cq * 8]);
            }
            cp_commit();
            cp_wait<1>();
        } else {
            cp_wait<0>();
        }
        __syncthreads();

        const __half* Ks = sm + cur * 2 * KVBUF;
        const __half* Vs = Ks + KVBUF;

        // ---- S = Qs @ K^T ----
        float s[8][4];
        #pragma unroll
        for (int nb = 0; nb < 8; nb++)
            #pragma unroll
            for (int j = 0; j < 4; j++) s[nb][j] = 0.0f;

        #pragma unroll
        for (int nb = 0; nb < 8; nb++) {
            #pragma unroll
            for (int kcp = 0; kcp < 2; kcp++) {
                uint32_t b0, b1, b2, b3;
                const __half* p = &Ks[(nb * 8 + r8) * KVP + kcp * 32 + m8 * 8];
                ldsm_x4(b0, b1, b2, b3, p);
                mma_f16(s[nb], qa[kcp * 2][0], qa[kcp * 2][1], qa[kcp * 2][2], qa[kcp * 2][3], b0, b1);
                mma_f16(s[nb], qa[kcp * 2 + 1][0], qa[kcp * 2 + 1][1], qa[kcp * 2 + 1][2], qa[kcp * 2 + 1][3], b2, b3);
            }
        }

        // ---- online softmax ----
        float rmax0 = -INFINITY, rmax1 = -INFINITY;
        #pragma unroll
        for (int nb = 0; nb < 8; nb++) {
            rmax0 = fmaxf(rmax0, fmaxf(s[nb][0], s[nb][1]));
            rmax1 = fmaxf(rmax1, fmaxf(s[nb][2], s[nb][3]));
        }
        rmax0 = fmaxf(rmax0, __shfl_xor_sync(0xffffffff, rmax0, 1));
        rmax0 = fmaxf(rmax0, __shfl_xor_sync(0xffffffff, rmax0, 2));
        rmax1 = fmaxf(rmax1, __shfl_xor_sync(0xffffffff, rmax1, 1));
        rmax1 = fmaxf(rmax1, __shfl_xor_sync(0xffffffff, rmax1, 2));

        float mn0 = fmaxf(m0, rmax0), mn1 = fmaxf(m1, rmax1);
        float al0 = __expf(m0 - mn0), al1 = __expf(m1 - mn1);
        m0 = mn0; m1 = mn1;
        const float ml0 = m0 * LOG2E_F, ml1 = m1 * LOG2E_F;

        // rescale O and l accumulators
        #pragma unroll
        for (int nb = 0; nb < 8; nb++) {
            o[nb][0] *= al0; o[nb][1] *= al0;
            o[nb][2] *= al1; o[nb][3] *= al1;
        }
        lacc[0] *= al0; lacc[1] *= al0; lacc[2] *= al1; lacc[3] *= al1;

        // ---- P = exp2((s-m)*log2e) directly as f16x2 fragments ----
        uint32_t pa[4][4];
        #pragma unroll
        for (int nb = 0; nb < 8; nb++) {
            float t0 = fmaf(s[nb][0], LOG2E_F, -ml0);
            float t1 = fmaf(s[nb][1], LOG2E_F, -ml0);
            float t2 = fmaf(s[nb][2], LOG2E_F, -ml1);
            float t3 = fmaf(s[nb][3], LOG2E_F, -ml1);
            uint32_t p01 = ex2h2(packh2(t0, t1));
            uint32_t p23 = ex2h2(packh2(t2, t3));
            pa[nb >> 1][(nb & 1) * 2 + 0] = p01;
            pa[nb >> 1][(nb & 1) * 2 + 1] = p23;
        }

        // ---- l += P @ ones (4 mma) ----
        #pragma unroll
        for (int j = 0; j < 4; j++)
            mma_f16(lacc, pa[j][0], pa[j][1], pa[j][2], pa[j][3], ONES_H2, ONES_H2);

        // ---- O += P @ V ----
        #pragma unroll
        for (int nb = 0; nb < 8; nb++) {
            #pragma unroll
            for (int kcp = 0; kcp < 2; kcp++) {
                uint32_t b0, b1, b2, b3;
                const __half* p = &Vs[(kcp * 32 + m8 * 8 + r8) * KVP + nb * 8];
                ldsm_x4_t(b0, b1, b2, b3, p);
                mma_f16(o[nb], pa[kcp * 2][0], pa[kcp * 2][1], pa[kcp * 2][2], pa[kcp * 2][3], b0, b1);
                mma_f16(o[nb], pa[kcp * 2 + 1][0], pa[kcp * 2 + 1][1], pa[kcp * 2 + 1][2], pa[kcp * 2 + 1][3], b2, b3);
            }
        }
        __syncthreads();
    }

    // ---- epilogue: O/l -> g_ctx fp16 [B*S, D] ----
    const int b = bh >> 3, h = bh & 7;
    const int row0 = warp * 16 + quad;
    const float inv0 = 1.0f / lacc[0], inv1 = 1.0f / lacc[2];
    const int s0 = blockIdx.x * 128 + row0;
    const int s1 = s0 + 8;
    #pragma unroll
    for (int nb = 0; nb < 8; nb++) {
        int d = nb * 8 + 2 * tg;
        *(uint32_t*)&g_ctx[((size_t)(b * Sq + s0)) * Dm + h * Hd + d] =
            packh2(o[nb][0] * inv0, o[nb][1] * inv0);
        *(uint32_t*)&g_ctx[((size_t)(b * Sq + s1)) * Dm + h * Hd + d] =
            packh2(o[nb][2] * inv1, o[nb][3] * inv1);
    }
}

// ---------------------------------------------------------------------------
extern "C" void kernel_launch(void* const* d_in, const int* in_sizes, int n_in,
                              void* d_out, int out_size)
{
    const float* x  = (const float*)d_in[0];
    const float* Wq = (const float*)d_in[1];
    const float* bq = (const float*)d_in[2];
    const float* Wk = (const float*)d_in[3];
    const float* bk = (const float*)d_in[4];
    const float* Wv = (const float*)d_in[5];
    const float* bv = (const float*)d_in[6];
    const float* Wo = (const float*)d_in[7];
    const float* bo = (const float*)d_in[8];
    float* out = (float*)d_out;

    cudaFuncSetAttribute(attn_kernel, cudaFuncAttributeMaxDynamicSharedMemorySize,
                         ATT_SMEM_BYTES);
    cudaFuncSetAttribute(proj_qkv_kernel, cudaFuncAttributeMaxDynamicSharedMemorySize,
                         PROJ_SMEM_BYTES);
    cudaFuncSetAttribute(proj_out_kernel, cudaFuncAttributeMaxDynamicSharedMemorySize,
                         PROJ_SMEM_BYTES);

    cvt_x_kernel<<<(Mrows * Dm) / (256 * 4), 256>>>(x);
    cvt_w_kernel<<<4 * DmDm / (256 * 4), 256>>>(Wq, Wk, Wv, Wo);
    proj_qkv_kernel<<<dim3(Dm / 64, Mrows / 128, 3), 256, PROJ_SMEM_BYTES>>>(bq, bk, bv);
    attn_kernel<<<dim3(Sq / 128, Bz * Hh), 256, ATT_SMEM_BYTES>>>();
    proj_out_kernel<<<dim3(Dm / 64, Mrows / 128), 256, PROJ_SMEM_BYTES>>>(bo, out);
}